// round 10
// baseline (speedup 1.0000x reference)
#include <cuda_runtime.h>
#include <math_constants.h>

// Problem constants
#define BB 16
#define NN 1024
#define MM 8192
#define MSPLIT 64
#define MCHUNK (MM / MSPLIT)      // 128 targets per block
#define TPB 128
#define PPT 8                     // binder points per thread (128*8 = 1024)
#define KPT 8                     // keys per thread in finalize (1024/128)
#define KSEL 204                  // int(0.2 * 1024)

// Scratch — plain stores only. Counter self-resets each launch.
__device__ float    g_part[MSPLIT][BB * NN];   // partial min d2 per split
__device__ float    g_rep [MSPLIT * BB];       // repel partial per (split,b)
__device__ unsigned g_cnt [BB];                // zero at load; reset each launch

__device__ __forceinline__ float sqrt_approx(float x) {
    float r; asm("sqrt.approx.f32 %0, %1;" : "=f"(r) : "f"(x));
    return r;
}

__global__ void __launch_bounds__(TPB) fused_kernel(
    const float* __restrict__ binder,   // [16,1024,3]
    const float* __restrict__ target,   // [8192,3]
    float* __restrict__ out)            // [16]
{
    __shared__ float4   s_tgt[MCHUNK];  // {-2x,-2y,-2z,|t|^2}  (2 KB)
    __shared__ float    s_warp[TPB / 32];
    __shared__ unsigned hist[256];
    __shared__ unsigned sh_sel, sh_rank;
    __shared__ int      sh_last;
    __shared__ float    s_fred[TPB / 32];
    __shared__ unsigned s_ured[TPB / 32];

    const int b     = blockIdx.x;
    const int split = blockIdx.y;
    const int tid   = threadIdx.x;
    const int lane  = tid & 31, wid = tid >> 5;
    const int mbase = split * MCHUNK;

    // One target per thread: t' = (-2t, |t|^2); s = t'.w + p.t'xyz; d2 = |p|^2 + s.
    {
        const float* t = target + (size_t)(mbase + tid) * 3;
        float x = t[0], y = t[1], z = t[2];
        s_tgt[tid] = make_float4(-2.f * x, -2.f * y, -2.f * z,
                                 fmaf(x, x, fmaf(y, y, z * z)));
    }

    // Register block of PPT binder points.
    float px[PPT], py[PPT], pz[PPT], cc[PPT], th[PPT];
    #pragma unroll
    for (int k = 0; k < PPT; ++k) {
        int n = tid + TPB * k;
        const float* p = binder + (size_t)(b * NN + n) * 3;
        px[k] = p[0]; py[k] = p[1]; pz[k] = p[2];
        cc[k] = fmaf(px[k], px[k], fmaf(py[k], py[k], pz[k] * pz[k]));
        th[k] = 9.f - cc[k];            // s < th  <=>  d2 < 9
    }
    __syncthreads();

    float m[PPT];
    #pragma unroll
    for (int k = 0; k < PPT; ++k) m[k] = CUDART_INF_F;
    float rep = 0.f;

    #pragma unroll 2
    for (int j = 0; j < MCHUNK; j += 2) {
        float4 t0 = s_tgt[j];           // LDS.128 broadcast
        float4 t1 = s_tgt[j + 1];

        float s0[PPT], s1[PPT], u[PPT];
        #pragma unroll
        for (int k = 0; k < PPT; ++k) {
            s0[k] = fmaf(px[k], t0.x, fmaf(py[k], t0.y, fmaf(pz[k], t0.z, t0.w)));
            s1[k] = fmaf(px[k], t1.x, fmaf(py[k], t1.y, fmaf(pz[k], t1.z, t1.w)));
            float dm = fminf(s0[k], s1[k]);
            m[k] = fminf(m[k], dm);
            u[k] = dm - th[k];          // < 0  <=> clash among this k's 2 targets
        }
        // Tree min (dep depth 3) for ONE branch per 16 pairs/lane.
        float v = fminf(fminf(fminf(u[0], u[1]), fminf(u[2], u[3])),
                        fminf(fminf(u[4], u[5]), fminf(u[6], u[7])));

        if (__builtin_expect(v < 0.f, 0)) {
            #pragma unroll
            for (int k = 0; k < PPT; ++k) {
                if (u[k] < 0.f) {
                    if (s0[k] < th[k]) {
                        float cl = 3.f - sqrt_approx(fmaxf(cc[k] + s0[k], 0.f));
                        rep = fmaf(cl, cl, rep);
                    }
                    if (s1[k] < th[k]) {
                        float cl = 3.f - sqrt_approx(fmaxf(cc[k] + s1[k], 0.f));
                        rep = fmaf(cl, cl, rep);
                    }
                }
            }
        }
    }

    // Partial min stores (coalesced), convert to d2-space and clamp.
    #pragma unroll
    for (int k = 0; k < PPT; ++k) {
        int n = tid + TPB * k;
        g_part[split][b * NN + n] = fmaxf(cc[k] + m[k], 0.f);
    }

    // Block repel partial.
    #pragma unroll
    for (int off = 16; off; off >>= 1)
        rep += __shfl_xor_sync(0xffffffffu, rep, off);
    if (lane == 0) s_warp[wid] = rep;
    __syncthreads();
    if (tid == 0) {
        float r = 0.f;
        #pragma unroll
        for (int w = 0; w < TPB / 32; ++w) r += s_warp[w];
        g_rep[split * BB + b] = r;
    }

    // ---- Last-block-done election for this batch ----
    __threadfence();
    __syncthreads();
    if (tid == 0) {
        unsigned old = atomicAdd(&g_cnt[b], 1u);
        sh_last = (old == MSPLIT - 1);
        if (sh_last) g_cnt[b] = 0;      // self-reset: identical state every launch
    }
    __syncthreads();
    if (!sh_last) return;
    __threadfence();

    // ---- Finalize for batch b (one block of 128 threads) ----
    unsigned keys[KPT];
    #pragma unroll
    for (int i = 0; i < KPT; ++i) {
        int n = tid + TPB * i;
        float mn = CUDART_INF_F;
        #pragma unroll
        for (int s = 0; s < MSPLIT; ++s)
            mn = fminf(mn, g_part[s][b * NN + n]);
        keys[i] = __float_as_uint(mn);  // non-negative: bit order == value order
    }

    if (tid == 0) sh_rank = KSEL;
    __syncthreads();

    // 4-pass MSB radix select for the KSEL-th smallest key.
    unsigned prefix = 0, prefmask = 0;
    #pragma unroll
    for (int pass = 0; pass < 4; ++pass) {
        const int shift = 24 - 8 * pass;
        hist[tid] = 0; hist[tid + 128] = 0;
        __syncthreads();
        #pragma unroll
        for (int i = 0; i < KPT; ++i)
            if ((keys[i] & prefmask) == prefix)
                atomicAdd(&hist[(keys[i] >> shift) & 255u], 1u);
        __syncthreads();
        if (tid < 32) {
            unsigned c8[8], tot = 0;
            #pragma unroll
            for (int i = 0; i < 8; ++i) { c8[i] = hist[tid * 8 + i]; tot += c8[i]; }
            unsigned incl = tot;
            #pragma unroll
            for (int off = 1; off < 32; off <<= 1) {
                unsigned x = __shfl_up_sync(0xffffffffu, incl, off);
                if (tid >= off) incl += x;
            }
            unsigned excl = incl - tot;
            unsigned r = sh_rank;
            __syncwarp();
            if (r > excl && r <= incl) {
                unsigned run = excl, sel = 0, nr = 0;
                #pragma unroll
                for (int i = 0; i < 8; ++i) {
                    if (run < r && r <= run + c8[i]) { sel = tid * 8 + i; nr = r - run; }
                    run += c8[i];
                }
                sh_sel  = sel;
                sh_rank = nr;
            }
        }
        __syncthreads();
        prefix   |= sh_sel << shift;
        prefmask |= 0xFFu   << shift;
    }
    const unsigned T = prefix;          // key of the KSEL-th smallest

    // Sum sqrt(d2) strictly below T; tie-correct with T.
    float ssum = 0.f; unsigned scnt = 0;
    #pragma unroll
    for (int i = 0; i < KPT; ++i)
        if (keys[i] < T) { ssum += sqrtf(__uint_as_float(keys[i])); scnt++; }
    #pragma unroll
    for (int off = 16; off; off >>= 1) {
        ssum += __shfl_xor_sync(0xffffffffu, ssum, off);
        scnt += __shfl_xor_sync(0xffffffffu, scnt, off);
    }
    if (lane == 0) { s_fred[wid] = ssum; s_ured[wid] = scnt; }
    __syncthreads();

    if (tid < 32) {
        float rp = g_rep[tid * BB + b] + g_rep[(tid + 32) * BB + b];
        #pragma unroll
        for (int off = 16; off; off >>= 1)
            rp += __shfl_xor_sync(0xffffffffu, rp, off);
        if (tid == 0) {
            float st = 0.f; unsigned ct = 0;
            #pragma unroll
            for (int w = 0; w < TPB / 32; ++w) { st += s_fred[w]; ct += s_ured[w]; }
            float attract = (st + (float)(KSEL - ct) * sqrtf(__uint_as_float(T)))
                            * (1.f / (float)KSEL);
            out[b] = 10.f * attract + 5.f * rp;
        }
    }
}

extern "C" void kernel_launch(void* const* d_in, const int* in_sizes, int n_in,
                              void* d_out, int out_size)
{
    const float* binder = (const float*)d_in[0];   // 16*1024*3
    const float* target = (const float*)d_in[1];   // 8192*3
    float* out = (float*)d_out;                    // 16

    dim3 grid(BB, MSPLIT);                         // 16 x 64 = 1024 blocks
    fused_kernel<<<grid, TPB>>>(binder, target, out);
}

// round 12
// speedup vs baseline: 2.0743x; 2.0743x over previous
#include <cuda_runtime.h>
#include <math_constants.h>

// Problem constants
#define BB 16
#define NN 1024
#define MM 8192
#define MSPLIT 54                 // 16*54 = 864 blocks ~ one full wave @6/SM
#define MCHUNK 152                // 54*152 = 8208 >= 8192; last split padded
#define TPB 256
#define PPT 4                     // binder points per thread (256*4 = 1024)
#define KSEL 204                  // int(0.2 * 1024)

// Scratch — all zero at load; finalize resets everything it consumes, so every
// graph replay sees identical initial state. No init kernel needed.
// Key encoding: key = ~bits(d2), d2 >= 0  ->  key > 0 always, larger key = smaller d2.
__device__ unsigned g_mind2u[BB * NN];   // atomicMax target; 0 = empty
__device__ float    g_rep   [BB];        // atomicAdd target; reset by finalize
__device__ unsigned g_cnt   [BB];        // arrival counter; self-resets

__device__ __forceinline__ float sqrt_approx(float x) {
    float r; asm("sqrt.approx.f32 %0, %1;" : "=f"(r) : "f"(x));
    return r;
}

__global__ void __launch_bounds__(TPB, 6) fused_kernel(
    const float* __restrict__ binder,   // [16,1024,3]
    const float* __restrict__ target,   // [8192,3]
    float* __restrict__ out)            // [16]
{
    __shared__ float4   s_tgt[MCHUNK];  // {-2x,-2y,-2z,|t|^2}; pad w=+inf
    __shared__ float    s_warp[TPB / 32];
    __shared__ unsigned hist[256];
    __shared__ unsigned sh_sel, sh_rank;
    __shared__ int      sh_last;
    __shared__ float    s_fred[TPB / 32];
    __shared__ unsigned s_ured[TPB / 32];

    const int split = blockIdx.x;       // 0..53
    const int b     = blockIdx.y;       // batch
    const int tid   = threadIdx.x;
    const int lane  = tid & 31, wid = tid >> 5;
    const int mbase = split * MCHUNK;

    // Target tile: t' = (-2t, |t|^2); s = t'.w + p.t'; d2 = |p|^2 + s.
    // Out-of-range rows get w=+inf -> s=+inf: never a min, never a clash.
    for (int j = tid; j < MCHUNK; j += TPB) {
        int mj = mbase + j;
        if (mj < MM) {
            const float* t = target + (size_t)mj * 3;
            float x = t[0], y = t[1], z = t[2];
            s_tgt[j] = make_float4(-2.f * x, -2.f * y, -2.f * z,
                                   fmaf(x, x, fmaf(y, y, z * z)));
        } else {
            s_tgt[j] = make_float4(0.f, 0.f, 0.f, CUDART_INF_F);
        }
    }

    // Register block of PPT binder points.
    float px[PPT], py[PPT], pz[PPT], cc[PPT], ccm9[PPT];
    #pragma unroll
    for (int k = 0; k < PPT; ++k) {
        int n = tid + TPB * k;
        const float* p = binder + (size_t)(b * NN + n) * 3;
        px[k] = p[0]; py[k] = p[1]; pz[k] = p[2];
        cc[k]   = fmaf(px[k], px[k], fmaf(py[k], py[k], pz[k] * pz[k]));
        ccm9[k] = cc[k] - 9.f;          // s + ccm9 < 0  <=>  d2 < 9
    }
    __syncthreads();

    float m[PPT];
    #pragma unroll
    for (int k = 0; k < PPT; ++k) m[k] = CUDART_INF_F;
    float rep = 0.f;

    #pragma unroll 2
    for (int j = 0; j < MCHUNK; j += 2) {   // uniform 76 iterations
        float4 t0 = s_tgt[j];               // LDS.128 broadcast
        float4 t1 = s_tgt[j + 1];

        float s0[PPT], s1[PPT], u[PPT];
        #pragma unroll
        for (int k = 0; k < PPT; ++k) {
            s0[k] = fmaf(px[k], t0.x, fmaf(py[k], t0.y, fmaf(pz[k], t0.z, t0.w)));
            s1[k] = fmaf(px[k], t1.x, fmaf(py[k], t1.y, fmaf(pz[k], t1.z, t1.w)));
            float sm = fminf(s0[k], s1[k]);
            m[k] = fminf(m[k], sm);
            u[k] = sm + ccm9[k];        // < 0 <=> clash among this k's 2 targets
        }
        // Tree min, ONE branch per 8 pairs/lane (256 pairs/warp, ~47% taken).
        float v = fminf(fminf(u[0], u[1]), fminf(u[2], u[3]));

        if (__builtin_expect(v < 0.f, 0)) {
            #pragma unroll
            for (int k = 0; k < PPT; ++k) {
                if (u[k] < 0.f) {
                    float e0 = s0[k] + ccm9[k];
                    float e1 = s1[k] + ccm9[k];
                    if (e0 < 0.f) {
                        float cl = 3.f - sqrt_approx(fmaxf(e0 + 9.f, 0.f));
                        rep = fmaf(cl, cl, rep);
                    }
                    if (e1 < 0.f) {
                        float cl = 3.f - sqrt_approx(fmaxf(e1 + 9.f, 0.f));
                        rep = fmaf(cl, cl, rep);
                    }
                }
            }
        }
    }

    // Cross-split min via atomicMax on ~bits (0 = empty, zero-init friendly).
    #pragma unroll
    for (int k = 0; k < PPT; ++k) {
        int n = tid + TPB * k;
        float d2 = fmaxf(cc[k] + m[k], 0.f);
        atomicMax(&g_mind2u[b * NN + n], ~__float_as_uint(d2));
    }

    // Block repel partial -> one atomicAdd per block.
    #pragma unroll
    for (int off = 16; off; off >>= 1)
        rep += __shfl_xor_sync(0xffffffffu, rep, off);
    if (lane == 0) s_warp[wid] = rep;
    __syncthreads();
    if (tid == 0) {
        float r = 0.f;
        #pragma unroll
        for (int w = 0; w < TPB / 32; ++w) r += s_warp[w];
        atomicAdd(&g_rep[b], r);
    }

    // ---- Last-block-done election for this batch ----
    __threadfence();
    __syncthreads();
    if (tid == 0) {
        unsigned old = atomicAdd(&g_cnt[b], 1u);
        sh_last = (old == MSPLIT - 1);
        if (sh_last) g_cnt[b] = 0;      // self-reset
    }
    __syncthreads();
    if (!sh_last) return;
    __threadfence();

    // ---- Finalize for batch b (one block of 256 threads) ----
    // Read keys, decode to d2 bit-space (ascending order), and RESET to 0 so
    // the next launch/replay starts from identical state.
    unsigned keys[4];
    #pragma unroll
    for (int i = 0; i < 4; ++i) {
        int n = tid + 256 * i;
        keys[i] = ~g_mind2u[b * NN + n];        // = bits(min d2)
        g_mind2u[b * NN + n] = 0u;
    }

    if (tid == 0) sh_rank = KSEL;
    __syncthreads();

    // 4-pass MSB radix select for the KSEL-th smallest d2.
    unsigned prefix = 0, prefmask = 0;
    #pragma unroll
    for (int pass = 0; pass < 4; ++pass) {
        const int shift = 24 - 8 * pass;
        hist[tid] = 0;
        __syncthreads();
        #pragma unroll
        for (int i = 0; i < 4; ++i)
            if ((keys[i] & prefmask) == prefix)
                atomicAdd(&hist[(keys[i] >> shift) & 255u], 1u);
        __syncthreads();
        if (tid < 32) {
            unsigned c8[8], tot = 0;
            #pragma unroll
            for (int i = 0; i < 8; ++i) { c8[i] = hist[tid * 8 + i]; tot += c8[i]; }
            unsigned incl = tot;
            #pragma unroll
            for (int off = 1; off < 32; off <<= 1) {
                unsigned x = __shfl_up_sync(0xffffffffu, incl, off);
                if (tid >= off) incl += x;
            }
            unsigned excl = incl - tot;
            unsigned r = sh_rank;
            __syncwarp();
            if (r > excl && r <= incl) {
                unsigned run = excl, sel = 0, nr = 0;
                #pragma unroll
                for (int i = 0; i < 8; ++i) {
                    if (run < r && r <= run + c8[i]) { sel = tid * 8 + i; nr = r - run; }
                    run += c8[i];
                }
                sh_sel  = sel;
                sh_rank = nr;
            }
        }
        __syncthreads();
        prefix   |= sh_sel << shift;
        prefmask |= 0xFFu   << shift;
    }
    const unsigned T = prefix;          // bits of the KSEL-th smallest d2

    // Sum sqrt(d2) strictly below T; tie-correct with T itself (exact).
    float ssum = 0.f; unsigned scnt = 0;
    #pragma unroll
    for (int i = 0; i < 4; ++i)
        if (keys[i] < T) { ssum += sqrtf(__uint_as_float(keys[i])); scnt++; }
    #pragma unroll
    for (int off = 16; off; off >>= 1) {
        ssum += __shfl_xor_sync(0xffffffffu, ssum, off);
        scnt += __shfl_xor_sync(0xffffffffu, scnt, off);
    }
    if (lane == 0) { s_fred[wid] = ssum; s_ured[wid] = scnt; }
    __syncthreads();

    if (tid == 0) {
        float st = 0.f; unsigned ct = 0;
        #pragma unroll
        for (int w = 0; w < TPB / 32; ++w) { st += s_fred[w]; ct += s_ured[w]; }
        float rp = g_rep[b];
        g_rep[b] = 0.f;                 // reset for next launch/replay
        float attract = (st + (float)(KSEL - ct) * sqrtf(__uint_as_float(T)))
                        * (1.f / (float)KSEL);
        out[b] = 10.f * attract + 5.f * rp;
    }
}

extern "C" void kernel_launch(void* const* d_in, const int* in_sizes, int n_in,
                              void* d_out, int out_size)
{
    const float* binder = (const float*)d_in[0];   // 16*1024*3
    const float* target = (const float*)d_in[1];   // 8192*3
    float* out = (float*)d_out;                    // 16

    dim3 grid(MSPLIT, BB);                         // 54 x 16 = 864 blocks
    fused_kernel<<<grid, TPB>>>(binder, target, out);
}

// round 13
// speedup vs baseline: 2.3121x; 1.1147x over previous
#include <cuda_runtime.h>
#include <math_constants.h>

// Problem constants
#define BB 16
#define NN 1024
#define MM 8192
#define MSPLIT 54                 // 16*54 = 864 blocks ~ one full wave @6/SM
#define MCHUNK 152                // 54*152 = 8208 >= 8192; last split padded
#define TPB 256
#define PPT 4                     // binder points per thread (256*4 = 1024)
#define KSEL 204                  // int(0.2 * 1024)

// Scratch — all zero at load; finalize resets everything it consumes, so every
// graph replay sees identical initial state. No init kernel needed.
// Key encoding: key = ~bits(d2), d2 >= 0  ->  key > 0 always, larger key = smaller d2.
__device__ unsigned g_mind2u[BB * NN];   // atomicMax target; 0 = empty
__device__ float    g_rep   [BB];        // atomicAdd target; reset by finalize
__device__ unsigned g_cnt   [BB];        // arrival counter; self-resets

__device__ __forceinline__ float sqrt_approx(float x) {
    float r; asm("sqrt.approx.f32 %0, %1;" : "=f"(r) : "f"(x));
    return r;
}

__global__ void __launch_bounds__(TPB, 6) fused_kernel(
    const float* __restrict__ binder,   // [16,1024,3]
    const float* __restrict__ target,   // [8192,3]
    float* __restrict__ out)            // [16]
{
    __shared__ float4   s_tgt[MCHUNK];  // {-2x,-2y,-2z,|t|^2}; pad w=+inf
    __shared__ float    s_warp[TPB / 32];
    __shared__ unsigned hist[256];
    __shared__ unsigned sh_sel, sh_rank;
    __shared__ int      sh_last;
    __shared__ float    s_fred[TPB / 32];
    __shared__ unsigned s_ured[TPB / 32];

    const int split = blockIdx.x;       // 0..53
    const int b     = blockIdx.y;       // batch
    const int tid   = threadIdx.x;
    const int lane  = tid & 31, wid = tid >> 5;
    const int mbase = split * MCHUNK;

    // Target tile: t' = (-2t, |t|^2); s = t'.w + p.t'; d2 = |p|^2 + s.
    // Out-of-range rows get w=+inf -> s=+inf: never a min, never a clash.
    for (int j = tid; j < MCHUNK; j += TPB) {
        int mj = mbase + j;
        if (mj < MM) {
            const float* t = target + (size_t)mj * 3;
            float x = t[0], y = t[1], z = t[2];
            s_tgt[j] = make_float4(-2.f * x, -2.f * y, -2.f * z,
                                   fmaf(x, x, fmaf(y, y, z * z)));
        } else {
            s_tgt[j] = make_float4(0.f, 0.f, 0.f, CUDART_INF_F);
        }
    }

    // Register block of PPT binder points.
    float px[PPT], py[PPT], pz[PPT], cc[PPT], ccm9[PPT];
    #pragma unroll
    for (int k = 0; k < PPT; ++k) {
        int n = tid + TPB * k;
        const float* p = binder + (size_t)(b * NN + n) * 3;
        px[k] = p[0]; py[k] = p[1]; pz[k] = p[2];
        cc[k]   = fmaf(px[k], px[k], fmaf(py[k], py[k], pz[k] * pz[k]));
        ccm9[k] = cc[k] - 9.f;          // s + ccm9 < 0  <=>  d2 < 9
    }
    __syncthreads();

    float m[PPT];
    #pragma unroll
    for (int k = 0; k < PPT; ++k) m[k] = CUDART_INF_F;
    float rep = 0.f;

    #pragma unroll 2
    for (int j = 0; j < MCHUNK; j += 2) {   // uniform 76 iterations
        float4 t0 = s_tgt[j];               // LDS.128 broadcast
        float4 t1 = s_tgt[j + 1];

        #pragma unroll
        for (int k = 0; k < PPT; ++k) {
            float s0 = fmaf(px[k], t0.x, fmaf(py[k], t0.y, fmaf(pz[k], t0.z, t0.w)));
            float s1 = fmaf(px[k], t1.x, fmaf(py[k], t1.y, fmaf(pz[k], t1.z, t1.w)));
            float sm = fminf(s0, s1);
            m[k] = fminf(m[k], sm);
            float u = sm + ccm9[k];     // < 0 <=> clash among this k's 2 targets

            // Per-k test (p ~ 15% taken per warp); flat branchless relu arm —
            // exact reference semantics: relu(3-d)^2, zero for non-clashers.
            if (__builtin_expect(u < 0.f, 0)) {
                float d2a = s0 + cc[k];
                float d2b = s1 + cc[k];
                float ca = fmaxf(3.f - sqrt_approx(d2a), 0.f);
                float cb = fmaxf(3.f - sqrt_approx(d2b), 0.f);
                rep = fmaf(ca, ca, rep);
                rep = fmaf(cb, cb, rep);
            }
        }
    }

    // Cross-split min via atomicMax on ~bits (0 = empty, zero-init friendly).
    #pragma unroll
    for (int k = 0; k < PPT; ++k) {
        int n = tid + TPB * k;
        float d2 = fmaxf(cc[k] + m[k], 0.f);
        atomicMax(&g_mind2u[b * NN + n], ~__float_as_uint(d2));
    }

    // Block repel partial -> one atomicAdd per block.
    #pragma unroll
    for (int off = 16; off; off >>= 1)
        rep += __shfl_xor_sync(0xffffffffu, rep, off);
    if (lane == 0) s_warp[wid] = rep;
    __syncthreads();
    if (tid == 0) {
        float r = 0.f;
        #pragma unroll
        for (int w = 0; w < TPB / 32; ++w) r += s_warp[w];
        atomicAdd(&g_rep[b], r);
    }

    // ---- Last-block-done election for this batch ----
    __threadfence();
    __syncthreads();
    if (tid == 0) {
        unsigned old = atomicAdd(&g_cnt[b], 1u);
        sh_last = (old == MSPLIT - 1);
        if (sh_last) g_cnt[b] = 0;      // self-reset
    }
    __syncthreads();
    if (!sh_last) return;
    __threadfence();

    // ---- Finalize for batch b (one block of 256 threads) ----
    // Read keys, decode to d2 bit-space (ascending order), and RESET to 0 so
    // the next launch/replay starts from identical state.
    unsigned keys[4];
    #pragma unroll
    for (int i = 0; i < 4; ++i) {
        int n = tid + 256 * i;
        keys[i] = ~g_mind2u[b * NN + n];        // = bits(min d2)
        g_mind2u[b * NN + n] = 0u;
    }

    if (tid == 0) sh_rank = KSEL;
    __syncthreads();

    // 4-pass MSB radix select for the KSEL-th smallest d2.
    unsigned prefix = 0, prefmask = 0;
    #pragma unroll
    for (int pass = 0; pass < 4; ++pass) {
        const int shift = 24 - 8 * pass;
        hist[tid] = 0;
        __syncthreads();
        #pragma unroll
        for (int i = 0; i < 4; ++i)
            if ((keys[i] & prefmask) == prefix)
                atomicAdd(&hist[(keys[i] >> shift) & 255u], 1u);
        __syncthreads();
        if (tid < 32) {
            unsigned c8[8], tot = 0;
            #pragma unroll
            for (int i = 0; i < 8; ++i) { c8[i] = hist[tid * 8 + i]; tot += c8[i]; }
            unsigned incl = tot;
            #pragma unroll
            for (int off = 1; off < 32; off <<= 1) {
                unsigned x = __shfl_up_sync(0xffffffffu, incl, off);
                if (tid >= off) incl += x;
            }
            unsigned excl = incl - tot;
            unsigned r = sh_rank;
            __syncwarp();
            if (r > excl && r <= incl) {
                unsigned run = excl, sel = 0, nr = 0;
                #pragma unroll
                for (int i = 0; i < 8; ++i) {
                    if (run < r && r <= run + c8[i]) { sel = tid * 8 + i; nr = r - run; }
                    run += c8[i];
                }
                sh_sel  = sel;
                sh_rank = nr;
            }
        }
        __syncthreads();
        prefix   |= sh_sel << shift;
        prefmask |= 0xFFu   << shift;
    }
    const unsigned T = prefix;          // bits of the KSEL-th smallest d2

    // Sum sqrt(d2) strictly below T; tie-correct with T itself (exact).
    float ssum = 0.f; unsigned scnt = 0;
    #pragma unroll
    for (int i = 0; i < 4; ++i)
        if (keys[i] < T) { ssum += sqrtf(__uint_as_float(keys[i])); scnt++; }
    #pragma unroll
    for (int off = 16; off; off >>= 1) {
        ssum += __shfl_xor_sync(0xffffffffu, ssum, off);
        scnt += __shfl_xor_sync(0xffffffffu, scnt, off);
    }
    if (lane == 0) { s_fred[wid] = ssum; s_ured[wid] = scnt; }
    __syncthreads();

    if (tid == 0) {
        float st = 0.f; unsigned ct = 0;
        #pragma unroll
        for (int w = 0; w < TPB / 32; ++w) { st += s_fred[w]; ct += s_ured[w]; }
        float rp = g_rep[b];
        g_rep[b] = 0.f;                 // reset for next launch/replay
        float attract = (st + (float)(KSEL - ct) * sqrtf(__uint_as_float(T)))
                        * (1.f / (float)KSEL);
        out[b] = 10.f * attract + 5.f * rp;
    }
}

extern "C" void kernel_launch(void* const* d_in, const int* in_sizes, int n_in,
                              void* d_out, int out_size)
{
    const float* binder = (const float*)d_in[0];   // 16*1024*3
    const float* target = (const float*)d_in[1];   // 8192*3
    float* out = (float*)d_out;                    // 16

    dim3 grid(MSPLIT, BB);                         // 54 x 16 = 864 blocks
    fused_kernel<<<grid, TPB>>>(binder, target, out);
}